// round 14
// baseline (speedup 1.0000x reference)
#include <cuda_runtime.h>
#include <cuda_fp16.h>
#include <math.h>
#include <stdint.h>

#define BB    32
#define TT    1024
#define CCH   512
#define CONDC 256
#define LLEN  252
#define SSEQ  128
#define MTOT  (BB*TT)

// fp16 GEMM: 128x128 block tile, BK=64, 3-stage cp.async, 256 thr (8 warps 4m x 2n)
#define BK        64
#define TILE_BYTES (128*128)              // 128 rows x 64 halves = 16 KB (A or B)
#define STAGE_BYTES (2*TILE_BYTES)        // 32 KB
#define STAGES    3
#define SMEM_BYTES (STAGES*STAGE_BYTES)   // 96 KB

// elementwise kernels: rows per block
#define EW_ROWS 32

// Scratch (static device globals: allocation-free per harness rules)
__device__ float  g_q[(size_t)MTOT * CCH];          // q fp32, later reused as z
__device__ float  g_query[(size_t)MTOT * CCH];      // fp32 (LN2 residual)
__device__ __half g_xh[(size_t)MTOT * CCH];
__device__ __half g_qh[(size_t)MTOT * CCH];         // half(query)
__device__ __half g_hh[(size_t)MTOT * 2 * CCH];     // half(h)
__device__ __half g_Wqh[CCH * CCH];
__device__ __half g_W1h[2 * CCH * CCH];
__device__ __half g_W2h[2 * CCH * CCH];
__device__ float g_Pk[BB * CCH];
__device__ float g_Pv[BB * CCH];
__device__ float g_WkSum[CCH];
__device__ float g_WvSum[CCH];

struct Params {
    const float *x, *cond_emb, *Wq, *bq, *Wk, *bk, *Wv, *bv,
                *conv_w, *conv_b, *ln1_w, *ln1_b, *W1, *b1, *W2, *b2,
                *ln2_w, *ln2_b;
};

// ---------------------------------------------------------------------------
// primitives
// ---------------------------------------------------------------------------
__device__ __forceinline__ void mma16(float* c, const uint32_t* a, const uint32_t* b) {
    asm volatile(
        "mma.sync.aligned.m16n8k16.row.col.f32.f16.f16.f32 "
        "{%0,%1,%2,%3}, {%4,%5,%6,%7}, {%8,%9}, {%0,%1,%2,%3};\n"
        : "+f"(c[0]), "+f"(c[1]), "+f"(c[2]), "+f"(c[3])
        : "r"(a[0]), "r"(a[1]), "r"(a[2]), "r"(a[3]), "r"(b[0]), "r"(b[1]));
}
__device__ __forceinline__ void ldsm4(uint32_t* r, uint32_t addr) {
    asm volatile("ldmatrix.sync.aligned.m8n8.x4.shared.b16 {%0,%1,%2,%3}, [%4];"
                 : "=r"(r[0]), "=r"(r[1]), "=r"(r[2]), "=r"(r[3]) : "r"(addr));
}
__device__ __forceinline__ void cpa(void* dst, const void* src) {
    unsigned d = (unsigned)__cvta_generic_to_shared(dst);
    asm volatile("cp.async.cg.shared.global [%0], [%1], 16;\n" :: "r"(d), "l"(src));
}
#define CP_COMMIT() asm volatile("cp.async.commit_group;\n")
template<int N> __device__ __forceinline__ void waitg() {
    asm volatile("cp.async.wait_group %0;\n" :: "n"(N));
}
__device__ __forceinline__ float wsum(float v) {
    #pragma unroll
    for (int o = 16; o; o >>= 1) v += __shfl_xor_sync(0xffffffffu, v, o);
    return v;
}
__device__ __forceinline__ float wmax(float v) {
    #pragma unroll
    for (int o = 16; o; o >>= 1) v = fmaxf(v, __shfl_xor_sync(0xffffffffu, v, o));
    return v;
}
__device__ __forceinline__ float dot4(float4 a, float4 b) {
    return fmaf(a.x, b.x, fmaf(a.y, b.y, fmaf(a.z, b.z, a.w * b.w)));
}

// ---------------------------------------------------------------------------
// Stage 128x64h A-tile and B-tile: row = 128B, chunk u(0..7), phys = u^(r&7)
// ---------------------------------------------------------------------------
__device__ __forceinline__ void load_tile_h(char* stage,
                                            const __half* __restrict__ A,
                                            const __half* __restrict__ Bw,
                                            int K, int k0, int tid) {
    const int u = tid & 7, r0 = tid >> 3;            // r0: 0..31
    char* As = stage;
    char* Bs = stage + TILE_BYTES;
    #pragma unroll
    for (int i = 0; i < 4; ++i) {
        const int r  = i * 32 + r0;
        const int ph = r * 128 + 16 * (u ^ (r & 7));
        cpa(As + ph, A  + (size_t)r * K + k0 + 8 * u);
        cpa(Bs + ph, Bw + (size_t)r * K + k0 + 8 * u);
    }
}

// ---------------------------------------------------------------------------
// fp16 GEMM: out[m0:+128, nbase:+128] = inp @ wgt^T  (both half, K-major)
// EPI: 0 = raw fp32 store, 1 = +bias, exact GELU, half store
// ---------------------------------------------------------------------------
template<int KDIM, int EPI>
__global__ __launch_bounds__(256, 2) void k_gemm_h(
    const __half* __restrict__ inp, const __half* __restrict__ wgt,
    const float* __restrict__ bias, void* __restrict__ outv, int Nout)
{
    extern __shared__ char sm[];
    const uint32_t smb = (uint32_t)__cvta_generic_to_shared(sm);
    const int tid  = threadIdx.x;
    const int lane = tid & 31, w = tid >> 5;
    const int wm = w & 3, wn = w >> 2;
    const int gid = lane >> 2, tig = lane & 3;
    const int m0 = blockIdx.x * 128, nbase = blockIdx.y * 128;
    const __half* A  = inp + (size_t)m0 * KDIM;
    const __half* Bw = wgt + (size_t)nbase * KDIM;

    float acc[2][8][4];
    #pragma unroll
    for (int mt = 0; mt < 2; ++mt)
        #pragma unroll
        for (int j = 0; j < 8; ++j)
            #pragma unroll
            for (int e = 0; e < 4; ++e) acc[mt][j][e] = 0.f;

    // per-lane ldmatrix row geometry (offsets within a stage)
    const int arow0 = wm * 32 + (lane & 15);          // A rows for mt=0 (mt adds 16)
    const uint32_t aoffA0 = arow0 * 128;
    const uint32_t aoffA1 = (arow0 + 16) * 128;
    const int aswz0 = arow0 & 7, aswz1 = (arow0 + 16) & 7;
    const int achunk = lane >> 4;                     // +0 or +1 16B chunk

    const int q = lane >> 3;
    const int brow0 = wn * 64 + (q >> 1) * 8 + (lane & 7);  // jp adds 16
    const int bchunk = q & 1;

    constexpr int NT = KDIM / BK;
    load_tile_h(sm + 0 * STAGE_BYTES, A, Bw, KDIM, 0 * BK, tid); CP_COMMIT();
    load_tile_h(sm + 1 * STAGE_BYTES, A, Bw, KDIM, 1 * BK, tid); CP_COMMIT();

    int cs = 0, ls = 2;
    #pragma unroll 1
    for (int t = 0; t < NT; ++t) {
        if (t + 1 < NT) waitg<1>(); else waitg<0>();
        __syncthreads();
        const uint32_t Ast = smb + cs * STAGE_BYTES;
        const uint32_t Bst = Ast + TILE_BYTES;

        #pragma unroll
        for (int ks = 0; ks < 4; ++ks) {
            const int c0 = 2 * ks;                    // 16B-chunk base for this k16
            uint32_t a[2][4];
            ldsm4(a[0], Ast + aoffA0 + 16 * ((c0 + achunk) ^ aswz0));
            ldsm4(a[1], Ast + aoffA1 + 16 * ((c0 + achunk) ^ aswz1));
            uint32_t b[8][2];
            #pragma unroll
            for (int jp = 0; jp < 4; ++jp) {
                const int br = brow0 + jp * 16;
                uint32_t r4[4];
                ldsm4(r4, Bst + br * 128 + 16 * ((c0 + bchunk) ^ (br & 7)));
                b[2 * jp][0] = r4[0]; b[2 * jp][1] = r4[1];
                b[2 * jp + 1][0] = r4[2]; b[2 * jp + 1][1] = r4[3];
            }
            #pragma unroll
            for (int mt = 0; mt < 2; ++mt)
                #pragma unroll
                for (int j = 0; j < 8; ++j)
                    mma16(acc[mt][j], a[mt], b[j]);
        }
        if (t + 2 < NT) {
            load_tile_h(sm + ls * STAGE_BYTES, A, Bw, KDIM, (t + 2) * BK, tid);
            CP_COMMIT();
        }
        if (++cs == STAGES) cs = 0;
        if (++ls == STAGES) ls = 0;
    }

    // epilogue: row = m0 + wm*32 + mt*16 + half*8 + gid ; col = nbase + wn*64 + j*8 + 2*tig
    #pragma unroll
    for (int mt = 0; mt < 2; ++mt)
        #pragma unroll
        for (int half = 0; half < 2; ++half) {
            const int row = m0 + wm * 32 + mt * 16 + half * 8 + gid;
            #pragma unroll
            for (int j = 0; j < 8; ++j) {
                const int c = nbase + wn * 64 + j * 8 + 2 * tig;
                float v0 = acc[mt][j][half * 2 + 0];
                float v1 = acc[mt][j][half * 2 + 1];
                if (EPI == 1) {
                    v0 += bias[c]; v1 += bias[c + 1];
                    v0 = 0.5f * v0 * (1.0f + erff(v0 * 0.70710678118654752f));
                    v1 = 0.5f * v1 * (1.0f + erff(v1 * 0.70710678118654752f));
                    *(__half2*)((__half*)outv + (size_t)row * Nout + c) =
                        __floats2half2_rn(v0, v1);
                } else {
                    *(float2*)((float*)outv + (size_t)row * Nout + c) =
                        make_float2(v0, v1);
                }
            }
        }
}

// ---------------------------------------------------------------------------
// fused fp32->fp16 conversion: 4 segments (x, Wq, W1, W2) in one launch
// ---------------------------------------------------------------------------
#define N4_X   (MTOT * CCH / 4)
#define N4_WQ  (CCH * CCH / 4)
#define N4_W1  (2 * CCH * CCH / 4)
#define N4_W2  (2 * CCH * CCH / 4)
#define BL_X   (N4_X  / 256)     // 16384
#define BL_WQ  (N4_WQ / 256)     // 256
#define BL_W1  (N4_W1 / 256)     // 512
#define BL_W2  (N4_W2 / 256)     // 512
#define BL_TOT (BL_X + BL_WQ + BL_W1 + BL_W2)

__global__ void k_f2h_all(const float* __restrict__ x, const float* __restrict__ wq,
                          const float* __restrict__ w1, const float* __restrict__ w2,
                          __half* __restrict__ xh, __half* __restrict__ wqh,
                          __half* __restrict__ w1h, __half* __restrict__ w2h) {
    int b = blockIdx.x;
    const float* in; __half* out;
    if (b < BL_X)                 { in = x;  out = xh; }
    else if ((b -= BL_X) < BL_WQ) { in = wq; out = wqh; }
    else if ((b -= BL_WQ) < BL_W1){ in = w1; out = w1h; }
    else { b -= BL_W1;              in = w2; out = w2h; }
    const int i = b * 256 + threadIdx.x;
    const float4 v = ((const float4*)in)[i];
    ((__half2*)out)[2 * i]     = __floats2half2_rn(v.x, v.y);
    ((__half2*)out)[2 * i + 1] = __floats2half2_rn(v.z, v.w);
}

// ---------------------------------------------------------------------------
// Precompute: Pk[b,c] = pad[b]·Wk[c,:], Pv likewise; plus weight row-sums
// ---------------------------------------------------------------------------
__global__ void k_precompute(Params p) {
    __shared__ float padS[CONDC];
    const int bb = blockIdx.x;
    const int which = blockIdx.y;
    const float* W = which ? p.Wv : p.Wk;

    if (bb == BB) {
        for (int c = threadIdx.x; c < CCH; c += blockDim.x) {
            float s = 0.f;
            const float* wr = W + (size_t)c * CONDC;
            #pragma unroll 4
            for (int j = 0; j < CONDC; ++j) s += wr[j];
            (which ? g_WvSum : g_WkSum)[c] = s;
        }
        return;
    }
    for (int j = threadIdx.x; j < CONDC; j += blockDim.x) {
        int src = (j + LLEN - 2) % LLEN;
        padS[j] = p.cond_emb[bb * LLEN + src];
    }
    __syncthreads();
    for (int c = threadIdx.x; c < CCH; c += blockDim.x) {
        float s = 0.f;
        const float* wr = W + (size_t)c * CONDC;
        #pragma unroll 4
        for (int j = 0; j < CONDC; ++j) s = fmaf(padS[j], wr[j], s);
        (which ? g_Pv : g_Pk)[bb * CCH + c] = s;
    }
}

// ---------------------------------------------------------------------------
// attn+LN1, 32 rows/block, warp handles 4 rows; all broadcast vectors in smem.
// smem layout (float4 index space): v*128 + i,  v: 0=bq 1=bk 2=bv 3=ln1w 4=ln1b
//                                               5=WkSum 6=WvSum 7=Pk[b] 8=Pv[b]
// ---------------------------------------------------------------------------
__global__ __launch_bounds__(256) void k_attn_ln1(Params p) {
    __shared__ float4 sp[9 * 128];
    __shared__ float convW[SSEQ], convB[SSEQ];
    const int tid = threadIdx.x;
    const int row0 = blockIdx.x * EW_ROWS;
    const int b = row0 >> 10;                        // EW_ROWS divides TT

    if (tid < SSEQ) { convW[tid] = p.conv_w[tid]; convB[tid] = p.conv_b[tid]; }
    {
        const float* srcs[9] = { p.bq, p.bk, p.bv, p.ln1_w, p.ln1_b,
                                 g_WkSum, g_WvSum, g_Pk + b * CCH, g_Pv + b * CCH };
        #pragma unroll
        for (int pass = 0; pass < 5; ++pass) {
            const int v = pass * 2 + (tid >> 7);
            if (v < 9) sp[v * 128 + (tid & 127)] = ((const float4*)srcs[v])[tid & 127];
        }
    }
    __syncthreads();

    const int lane = tid & 31, w = tid >> 5;
    const float4* bq4 = sp;
    const float4* bk4 = sp + 128;
    const float4* bv4 = sp + 256;
    const float4* lw4 = sp + 384;
    const float4* lb4 = sp + 512;
    const float4* Wk4 = sp + 640;
    const float4* Wv4 = sp + 768;
    const float4* Pk4 = sp + 896;
    const float4* Pv4 = sp + 1024;
    const float scl = 0.04419417382415922f;          // 1/sqrt(512)

    #pragma unroll 1
    for (int rr = 0; rr < 4; ++rr) {
        const int row = row0 + w * 4 + rr;
        const float4* qr4 = (const float4*)(g_q + (size_t)row * CCH);

        float4 qv[4];
        float u = 0.f, vv = 0.f, c0 = 0.f;
        #pragma unroll
        for (int j = 0; j < 4; ++j) {
            const int c4 = j * 32 + lane;
            float4 q4 = qr4[c4];
            const float4 bq = bq4[c4];
            q4.x += bq.x; q4.y += bq.y; q4.z += bq.z; q4.w += bq.w;
            qv[j] = q4;
            u  += dot4(q4, Pk4[c4]);
            vv += dot4(q4, Wk4[c4]);
            c0 += dot4(q4, bk4[c4]);
        }
        u = wsum(u); vv = wsum(vv); c0 = wsum(c0);

        float sc[4], mx = -3.4e38f;
        #pragma unroll
        for (int ss = 0; ss < 4; ++ss) {
            const int s = lane + 32 * ss;
            sc[ss] = scl * (convW[s] * u + convB[s] * vv + c0);
            mx = fmaxf(mx, sc[ss]);
        }
        mx = wmax(mx);
        float z = 0.f, a1 = 0.f, a2 = 0.f;
        #pragma unroll
        for (int ss = 0; ss < 4; ++ss) {
            const int s = lane + 32 * ss;
            const float e = expf(sc[ss] - mx);
            z += e; a1 = fmaf(e, convW[s], a1); a2 = fmaf(e, convB[s], a2);
        }
        z = wsum(z); a1 = wsum(a1); a2 = wsum(a2);
        const float w1 = a1 / z, w2 = a2 / z;

        float s1 = 0.f, s2 = 0.f;
        #pragma unroll
        for (int j = 0; j < 4; ++j) {
            const int c4 = j * 32 + lane;
            const float4 pv = Pv4[c4], wv = Wv4[c4], bv = bv4[c4];
            float4 y;
            y.x = qv[j].x + fmaf(w1, pv.x, fmaf(w2, wv.x, bv.x));
            y.y = qv[j].y + fmaf(w1, pv.y, fmaf(w2, wv.y, bv.y));
            y.z = qv[j].z + fmaf(w1, pv.z, fmaf(w2, wv.z, bv.z));
            y.w = qv[j].w + fmaf(w1, pv.w, fmaf(w2, wv.w, bv.w));
            qv[j] = y;
            s1 += y.x + y.y + y.z + y.w;
            s2 += y.x * y.x + y.y * y.y + y.z * y.z + y.w * y.w;
        }
        s1 = wsum(s1); s2 = wsum(s2);
        const float mu = s1 * (1.f / CCH);
        const float rs = rsqrtf(s2 * (1.f / CCH) - mu * mu + 1e-5f);

        float4* qo4 = (float4*)(g_query + (size_t)row * CCH);
        __half* qoh = g_qh + (size_t)row * CCH;
        #pragma unroll
        for (int j = 0; j < 4; ++j) {
            const int c4 = j * 32 + lane;
            const float4 lw = lw4[c4], lb = lb4[c4];
            float4 o;
            o.x = (qv[j].x - mu) * rs * lw.x + lb.x;
            o.y = (qv[j].y - mu) * rs * lw.y + lb.y;
            o.z = (qv[j].z - mu) * rs * lw.z + lb.z;
            o.w = (qv[j].w - mu) * rs * lw.w + lb.w;
            qo4[c4] = o;
            *(__half2*)(qoh + 4 * c4)     = __floats2half2_rn(o.x, o.y);
            *(__half2*)(qoh + 4 * c4 + 2) = __floats2half2_rn(o.z, o.w);
        }
    }
}

// ---------------------------------------------------------------------------
// LN2, 32 rows/block, warp handles 4 rows; b2/ln2_w/ln2_b in smem.
// out = LN2(z + b2 + query) + x   (z lives in g_q)
// ---------------------------------------------------------------------------
__global__ __launch_bounds__(256) void k_ln2(Params p, float* __restrict__ out) {
    __shared__ float4 sp[3 * 128];                   // 0=b2 1=ln2w 2=ln2b
    const int tid = threadIdx.x;
    const int row0 = blockIdx.x * EW_ROWS;
    {
        const float* srcs[3] = { p.b2, p.ln2_w, p.ln2_b };
        #pragma unroll
        for (int pass = 0; pass < 2; ++pass) {
            const int v = pass * 2 + (tid >> 7);
            if (v < 3) sp[v * 128 + (tid & 127)] = ((const float4*)srcs[v])[tid & 127];
        }
    }
    __syncthreads();

    const int lane = tid & 31, w = tid >> 5;
    const float4* b24 = sp;
    const float4* lw4 = sp + 128;
    const float4* lb4 = sp + 256;

    #pragma unroll 1
    for (int rr = 0; rr < 4; ++rr) {
        const int row = row0 + w * 4 + rr;
        const float4* zr4 = (const float4*)(g_q     + (size_t)row * CCH);
        const float4* qr4 = (const float4*)(g_query + (size_t)row * CCH);
        const float4* xr4 = (const float4*)(p.x     + (size_t)row * CCH);

        float4 yv[4];
        float s1 = 0.f, s2 = 0.f;
        #pragma unroll
        for (int j = 0; j < 4; ++j) {
            const int c4 = j * 32 + lane;
            const float4 z4 = zr4[c4], q4 = qr4[c4], b4 = b24[c4];
            float4 y;
            y.x = z4.x + b4.x + q4.x;
            y.y = z4.y + b4.y + q4.y;
            y.z = z4.z + b4.z + q4.z;
            y.w = z4.w + b4.w + q4.w;
            yv[j] = y;
            s1 += y.x + y.y + y.z + y.w;
            s2 += y.x * y.x + y.y * y.y + y.z * y.z + y.w * y.w;
        }
        s1 = wsum(s1); s2 = wsum(s2);
        const float mu = s1 * (1.f / CCH);
        const float rs = rsqrtf(s2 * (1.f / CCH) - mu * mu + 1e-5f);

        float4* o4 = (float4*)(out + (size_t)row * CCH);
        #pragma unroll
        for (int j = 0; j < 4; ++j) {
            const int c4 = j * 32 + lane;
            const float4 lw = lw4[c4], lb = lb4[c4], x4 = xr4[c4];
            float4 o;
            o.x = (yv[j].x - mu) * rs * lw.x + lb.x + x4.x;
            o.y = (yv[j].y - mu) * rs * lw.y + lb.y + x4.y;
            o.z = (yv[j].z - mu) * rs * lw.z + lb.z + x4.z;
            o.w = (yv[j].w - mu) * rs * lw.w + lb.w + x4.w;
            o4[c4] = o;
        }
    }
}

// ---------------------------------------------------------------------------
extern "C" void kernel_launch(void* const* d_in, const int* in_sizes, int n_in,
                              void* d_out, int out_size) {
    Params p;
    p.x        = (const float*)d_in[0];
    p.cond_emb = (const float*)d_in[1];
    p.Wq       = (const float*)d_in[2];
    p.bq       = (const float*)d_in[3];
    p.Wk       = (const float*)d_in[4];
    p.bk       = (const float*)d_in[5];
    p.Wv       = (const float*)d_in[6];
    p.bv       = (const float*)d_in[7];
    p.conv_w   = (const float*)d_in[8];
    p.conv_b   = (const float*)d_in[9];
    p.ln1_w    = (const float*)d_in[10];
    p.ln1_b    = (const float*)d_in[11];
    p.W1       = (const float*)d_in[12];
    p.b1       = (const float*)d_in[13];
    p.W2       = (const float*)d_in[14];
    p.b2       = (const float*)d_in[15];
    p.ln2_w    = (const float*)d_in[16];
    p.ln2_b    = (const float*)d_in[17];
    float* out = (float*)d_out;

    static bool attr_done = false;
    if (!attr_done) {
        cudaFuncSetAttribute(k_gemm_h<512, 0>,  cudaFuncAttributeMaxDynamicSharedMemorySize, SMEM_BYTES);
        cudaFuncSetAttribute(k_gemm_h<512, 1>,  cudaFuncAttributeMaxDynamicSharedMemorySize, SMEM_BYTES);
        cudaFuncSetAttribute(k_gemm_h<1024, 0>, cudaFuncAttributeMaxDynamicSharedMemorySize, SMEM_BYTES);
        attr_done = true;
    }

    float *dq;
    __half *dxh, *dqh, *dhh, *dWqh, *dW1h, *dW2h;
    cudaGetSymbolAddress((void**)&dq,   g_q);
    cudaGetSymbolAddress((void**)&dxh,  g_xh);
    cudaGetSymbolAddress((void**)&dqh,  g_qh);
    cudaGetSymbolAddress((void**)&dhh,  g_hh);
    cudaGetSymbolAddress((void**)&dWqh, g_Wqh);
    cudaGetSymbolAddress((void**)&dW1h, g_W1h);
    cudaGetSymbolAddress((void**)&dW2h, g_W2h);

    k_precompute<<<dim3(BB + 1, 2), 256>>>(p);
    k_f2h_all<<<BL_TOT, 256>>>(p.x, p.Wq, p.W1, p.W2, dxh, dWqh, dW1h, dW2h);

    // q = x @ Wq^T (fp32 out; bias folded into attn kernel)
    k_gemm_h<512, 0><<<dim3(MTOT / 128, 4), 256, SMEM_BYTES>>>(dxh, dWqh, nullptr, dq, CCH);
    k_attn_ln1<<<MTOT / EW_ROWS, 256>>>(p);
    // h = gelu(query @ W1^T + b1) (half out)
    k_gemm_h<512, 1><<<dim3(MTOT / 128, 8), 256, SMEM_BYTES>>>(dqh, dW1h, p.b1, dhh, 2 * CCH);
    // z = h @ W2^T (fp32 out; bias in ln2) -> reuse g_q
    k_gemm_h<1024, 0><<<dim3(MTOT / 128, 4), 256, SMEM_BYTES>>>(dhh, dW2h, nullptr, dq, CCH);
    k_ln2<<<MTOT / EW_ROWS, 256>>>(p, out);
}

// round 17
// speedup vs baseline: 1.0741x; 1.0741x over previous
#include <cuda_runtime.h>
#include <cuda_fp16.h>
#include <math.h>
#include <stdint.h>

#define BB    32
#define TT    1024
#define CCH   512
#define CONDC 256
#define LLEN  252
#define SSEQ  128
#define MTOT  (BB*TT)

// fp16 GEMM: 128x128 block tile, BK=64, 3-stage cp.async, 256 thr (8 warps 4m x 2n)
#define BK        64
#define TILE_BYTES (128*128)              // 128 rows x 64 halves = 16 KB (A or B)
#define STAGE_BYTES (2*TILE_BYTES)        // 32 KB
#define STAGES    3
#define SMEM_BYTES (STAGES*STAGE_BYTES)   // 96 KB

// Scratch (static device globals: allocation-free per harness rules)
__device__ float  g_q[(size_t)MTOT * CCH];          // q fp32 (qproj -> attn)
__device__ __half g_xh[(size_t)MTOT * CCH];         // half(x); reused as half(z)
__device__ __half g_qh[(size_t)MTOT * CCH];         // half(query) - GEMM A + residual
__device__ __half g_hh[(size_t)MTOT * 2 * CCH];     // half(h)
__device__ __half g_Wqh[CCH * CCH];
__device__ __half g_W1h[2 * CCH * CCH];
__device__ __half g_W2h[2 * CCH * CCH];
__device__ float g_Pk[BB * CCH];
__device__ float g_Pv[BB * CCH];
__device__ float g_WkSum[CCH];
__device__ float g_WvSum[CCH];

struct Params {
    const float *x, *cond_emb, *Wq, *bq, *Wk, *bk, *Wv, *bv,
                *conv_w, *conv_b, *ln1_w, *ln1_b, *W1, *b1, *W2, *b2,
                *ln2_w, *ln2_b;
};

// ---------------------------------------------------------------------------
// primitives
// ---------------------------------------------------------------------------
__device__ __forceinline__ void mma16(float* c, const uint32_t* a, const uint32_t* b) {
    asm volatile(
        "mma.sync.aligned.m16n8k16.row.col.f32.f16.f16.f32 "
        "{%0,%1,%2,%3}, {%4,%5,%6,%7}, {%8,%9}, {%0,%1,%2,%3};\n"
        : "+f"(c[0]), "+f"(c[1]), "+f"(c[2]), "+f"(c[3])
        : "r"(a[0]), "r"(a[1]), "r"(a[2]), "r"(a[3]), "r"(b[0]), "r"(b[1]));
}
__device__ __forceinline__ void ldsm4(uint32_t* r, uint32_t addr) {
    asm volatile("ldmatrix.sync.aligned.m8n8.x4.shared.b16 {%0,%1,%2,%3}, [%4];"
                 : "=r"(r[0]), "=r"(r[1]), "=r"(r[2]), "=r"(r[3]) : "r"(addr));
}
__device__ __forceinline__ void cpa(void* dst, const void* src) {
    unsigned d = (unsigned)__cvta_generic_to_shared(dst);
    asm volatile("cp.async.cg.shared.global [%0], [%1], 16;\n" :: "r"(d), "l"(src));
}
#define CP_COMMIT() asm volatile("cp.async.commit_group;\n")
template<int N> __device__ __forceinline__ void waitg() {
    asm volatile("cp.async.wait_group %0;\n" :: "n"(N));
}
__device__ __forceinline__ float wsum(float v) {
    #pragma unroll
    for (int o = 16; o; o >>= 1) v += __shfl_xor_sync(0xffffffffu, v, o);
    return v;
}
__device__ __forceinline__ float wmax(float v) {
    #pragma unroll
    for (int o = 16; o; o >>= 1) v = fmaxf(v, __shfl_xor_sync(0xffffffffu, v, o));
    return v;
}
__device__ __forceinline__ float dot4(float4 a, float4 b) {
    return fmaf(a.x, b.x, fmaf(a.y, b.y, fmaf(a.z, b.z, a.w * b.w)));
}

// ---------------------------------------------------------------------------
// Stage 128x64h A-tile and B-tile: row = 128B, chunk u(0..7), phys = u^(r&7)
// ---------------------------------------------------------------------------
__device__ __forceinline__ void load_tile_h(char* stage,
                                            const __half* __restrict__ A,
                                            const __half* __restrict__ Bw,
                                            int K, int k0, int tid) {
    const int u = tid & 7, r0 = tid >> 3;            // r0: 0..31
    char* As = stage;
    char* Bs = stage + TILE_BYTES;
    #pragma unroll
    for (int i = 0; i < 4; ++i) {
        const int r  = i * 32 + r0;
        const int ph = r * 128 + 16 * (u ^ (r & 7));
        cpa(As + ph, A  + (size_t)r * K + k0 + 8 * u);
        cpa(Bs + ph, Bw + (size_t)r * K + k0 + 8 * u);
    }
}

// ---------------------------------------------------------------------------
// fp16 GEMM: out[m0:+128, nbase:+128] = inp @ wgt^T  (both half, K-major)
// EPI: 0 = raw fp32 store, 1 = +bias exact GELU half store, 2 = raw half store
// ---------------------------------------------------------------------------
template<int KDIM, int EPI>
__global__ __launch_bounds__(256, 2) void k_gemm_h(
    const __half* __restrict__ inp, const __half* __restrict__ wgt,
    const float* __restrict__ bias, void* __restrict__ outv, int Nout)
{
    extern __shared__ char sm[];
    const uint32_t smb = (uint32_t)__cvta_generic_to_shared(sm);
    const int tid  = threadIdx.x;
    const int lane = tid & 31, w = tid >> 5;
    const int wm = w & 3, wn = w >> 2;
    const int gid = lane >> 2, tig = lane & 3;
    const int m0 = blockIdx.x * 128, nbase = blockIdx.y * 128;
    const __half* A  = inp + (size_t)m0 * KDIM;
    const __half* Bw = wgt + (size_t)nbase * KDIM;

    float acc[2][8][4];
    #pragma unroll
    for (int mt = 0; mt < 2; ++mt)
        #pragma unroll
        for (int j = 0; j < 8; ++j)
            #pragma unroll
            for (int e = 0; e < 4; ++e) acc[mt][j][e] = 0.f;

    // per-lane ldmatrix row geometry (offsets within a stage)
    const int arow0 = wm * 32 + (lane & 15);          // A rows for mt=0 (mt adds 16)
    const uint32_t aoffA0 = arow0 * 128;
    const uint32_t aoffA1 = (arow0 + 16) * 128;
    const int aswz0 = arow0 & 7, aswz1 = (arow0 + 16) & 7;
    const int achunk = lane >> 4;                     // +0 or +1 16B chunk

    const int q = lane >> 3;
    const int brow0 = wn * 64 + (q >> 1) * 8 + (lane & 7);  // jp adds 16
    const int bchunk = q & 1;

    constexpr int NT = KDIM / BK;
    load_tile_h(sm + 0 * STAGE_BYTES, A, Bw, KDIM, 0 * BK, tid); CP_COMMIT();
    load_tile_h(sm + 1 * STAGE_BYTES, A, Bw, KDIM, 1 * BK, tid); CP_COMMIT();

    int cs = 0, ls = 2;
    #pragma unroll 1
    for (int t = 0; t < NT; ++t) {
        if (t + 1 < NT) waitg<1>(); else waitg<0>();
        __syncthreads();
        const uint32_t Ast = smb + cs * STAGE_BYTES;
        const uint32_t Bst = Ast + TILE_BYTES;

        #pragma unroll
        for (int ks = 0; ks < 4; ++ks) {
            const int c0 = 2 * ks;                    // 16B-chunk base for this k16
            uint32_t a[2][4];
            ldsm4(a[0], Ast + aoffA0 + 16 * ((c0 + achunk) ^ aswz0));
            ldsm4(a[1], Ast + aoffA1 + 16 * ((c0 + achunk) ^ aswz1));
            uint32_t b[8][2];
            #pragma unroll
            for (int jp = 0; jp < 4; ++jp) {
                const int br = brow0 + jp * 16;
                uint32_t r4[4];
                ldsm4(r4, Bst + br * 128 + 16 * ((c0 + bchunk) ^ (br & 7)));
                b[2 * jp][0] = r4[0]; b[2 * jp][1] = r4[1];
                b[2 * jp + 1][0] = r4[2]; b[2 * jp + 1][1] = r4[3];
            }
            #pragma unroll
            for (int mt = 0; mt < 2; ++mt)
                #pragma unroll
                for (int j = 0; j < 8; ++j)
                    mma16(acc[mt][j], a[mt], b[j]);
        }
        if (t + 2 < NT) {
            load_tile_h(sm + ls * STAGE_BYTES, A, Bw, KDIM, (t + 2) * BK, tid);
            CP_COMMIT();
        }
        if (++cs == STAGES) cs = 0;
        if (++ls == STAGES) ls = 0;
    }

    // epilogue: row = m0 + wm*32 + mt*16 + half*8 + gid ; col = nbase + wn*64 + j*8 + 2*tig
    #pragma unroll
    for (int mt = 0; mt < 2; ++mt)
        #pragma unroll
        for (int half = 0; half < 2; ++half) {
            const int row = m0 + wm * 32 + mt * 16 + half * 8 + gid;
            #pragma unroll
            for (int j = 0; j < 8; ++j) {
                const int c = nbase + wn * 64 + j * 8 + 2 * tig;
                float v0 = acc[mt][j][half * 2 + 0];
                float v1 = acc[mt][j][half * 2 + 1];
                if (EPI == 1) {
                    v0 += bias[c]; v1 += bias[c + 1];
                    v0 = 0.5f * v0 * (1.0f + erff(v0 * 0.70710678118654752f));
                    v1 = 0.5f * v1 * (1.0f + erff(v1 * 0.70710678118654752f));
                    *(__half2*)((__half*)outv + (size_t)row * Nout + c) =
                        __floats2half2_rn(v0, v1);
                } else if (EPI == 2) {
                    *(__half2*)((__half*)outv + (size_t)row * Nout + c) =
                        __floats2half2_rn(v0, v1);
                } else {
                    *(float2*)((float*)outv + (size_t)row * Nout + c) =
                        make_float2(v0, v1);
                }
            }
        }
}

// ---------------------------------------------------------------------------
// fused fp32->fp16 conversion: 4 segments (x, Wq, W1, W2) in one launch
// ---------------------------------------------------------------------------
#define N4_X   (MTOT * CCH / 4)
#define N4_WQ  (CCH * CCH / 4)
#define N4_W1  (2 * CCH * CCH / 4)
#define N4_W2  (2 * CCH * CCH / 4)
#define BL_X   (N4_X  / 256)     // 16384
#define BL_WQ  (N4_WQ / 256)     // 256
#define BL_W1  (N4_W1 / 256)     // 512
#define BL_W2  (N4_W2 / 256)     // 512
#define BL_TOT (BL_X + BL_WQ + BL_W1 + BL_W2)

__global__ void k_f2h_all(const float* __restrict__ x, const float* __restrict__ wq,
                          const float* __restrict__ w1, const float* __restrict__ w2,
                          __half* __restrict__ xh, __half* __restrict__ wqh,
                          __half* __restrict__ w1h, __half* __restrict__ w2h) {
    int b = blockIdx.x;
    const float* in; __half* out;
    if (b < BL_X)                 { in = x;  out = xh; }
    else if ((b -= BL_X) < BL_WQ) { in = wq; out = wqh; }
    else if ((b -= BL_WQ) < BL_W1){ in = w1; out = w1h; }
    else { b -= BL_W1;              in = w2; out = w2h; }
    const int i = b * 256 + threadIdx.x;
    const float4 v = ((const float4*)in)[i];
    ((__half2*)out)[2 * i]     = __floats2half2_rn(v.x, v.y);
    ((__half2*)out)[2 * i + 1] = __floats2half2_rn(v.z, v.w);
}

// ---------------------------------------------------------------------------
// Precompute: Pk[b,c] = pad[b]·Wk[c,:], Pv likewise; plus weight row-sums
// ---------------------------------------------------------------------------
__global__ void k_precompute(Params p) {
    __shared__ float padS[CONDC];
    const int bb = blockIdx.x;
    const int which = blockIdx.y;
    const float* W = which ? p.Wv : p.Wk;

    if (bb == BB) {
        for (int c = threadIdx.x; c < CCH; c += blockDim.x) {
            float s = 0.f;
            const float* wr = W + (size_t)c * CONDC;
            #pragma unroll 4
            for (int j = 0; j < CONDC; ++j) s += wr[j];
            (which ? g_WvSum : g_WkSum)[c] = s;
        }
        return;
    }
    for (int j = threadIdx.x; j < CONDC; j += blockDim.x) {
        int src = (j + LLEN - 2) % LLEN;
        padS[j] = p.cond_emb[bb * LLEN + src];
    }
    __syncthreads();
    for (int c = threadIdx.x; c < CCH; c += blockDim.x) {
        float s = 0.f;
        const float* wr = W + (size_t)c * CONDC;
        #pragma unroll 4
        for (int j = 0; j < CONDC; ++j) s = fmaf(padS[j], wr[j], s);
        (which ? g_Pv : g_Pk)[bb * CCH + c] = s;
    }
}

// ---------------------------------------------------------------------------
// Warp-per-row, float4 (r13 layout): q=g_q+bq -> rank-1 attention -> +LN1
// output: HALF only (g_qh) — consumed by ffn1 GEMM and ln2 residual.
// ---------------------------------------------------------------------------
__global__ __launch_bounds__(256) void k_attn_ln1(Params p) {
    __shared__ float convW[SSEQ], convB[SSEQ];
    const int tid = threadIdx.x;
    if (tid < SSEQ) { convW[tid] = p.conv_w[tid]; convB[tid] = p.conv_b[tid]; }
    __syncthreads();

    const int lane = tid & 31, w = tid >> 5;
    const int row = blockIdx.x * 8 + w;
    const int b = row >> 10;
    const float4* qr4 = (const float4*)(g_q + (size_t)row * CCH);
    const float4* Pk4 = (const float4*)(g_Pk + b * CCH);
    const float4* Pv4 = (const float4*)(g_Pv + b * CCH);
    const float4* Wk4 = (const float4*)g_WkSum;
    const float4* Wv4 = (const float4*)g_WvSum;
    const float4* bq4 = (const float4*)p.bq;
    const float4* bk4 = (const float4*)p.bk;
    const float4* bv4 = (const float4*)p.bv;

    float4 qv[4];
    float u = 0.f, vv = 0.f, c0 = 0.f;
    #pragma unroll
    for (int j = 0; j < 4; ++j) {
        const int c4 = j * 32 + lane;
        float4 q4 = qr4[c4];
        const float4 bq = bq4[c4];
        q4.x += bq.x; q4.y += bq.y; q4.z += bq.z; q4.w += bq.w;
        qv[j] = q4;
        u  += dot4(q4, Pk4[c4]);
        vv += dot4(q4, Wk4[c4]);
        c0 += dot4(q4, bk4[c4]);
    }
    u = wsum(u); vv = wsum(vv); c0 = wsum(c0);

    const float scl = 0.04419417382415922f;   // 1/sqrt(512)
    float sc[4], mx = -3.4e38f;
    #pragma unroll
    for (int ss = 0; ss < 4; ++ss) {
        const int s = lane + 32 * ss;
        sc[ss] = scl * (convW[s] * u + convB[s] * vv + c0);
        mx = fmaxf(mx, sc[ss]);
    }
    mx = wmax(mx);
    float z = 0.f, a1 = 0.f, a2 = 0.f;
    #pragma unroll
    for (int ss = 0; ss < 4; ++ss) {
        const int s = lane + 32 * ss;
        const float e = expf(sc[ss] - mx);
        z += e; a1 = fmaf(e, convW[s], a1); a2 = fmaf(e, convB[s], a2);
    }
    z = wsum(z); a1 = wsum(a1); a2 = wsum(a2);
    const float w1 = a1 / z, w2 = a2 / z;

    float s1 = 0.f, s2 = 0.f;
    #pragma unroll
    for (int j = 0; j < 4; ++j) {
        const int c4 = j * 32 + lane;
        const float4 pv = Pv4[c4], wv = Wv4[c4], bv = bv4[c4];
        float4 y;
        y.x = qv[j].x + fmaf(w1, pv.x, fmaf(w2, wv.x, bv.x));
        y.y = qv[j].y + fmaf(w1, pv.y, fmaf(w2, wv.y, bv.y));
        y.z = qv[j].z + fmaf(w1, pv.z, fmaf(w2, wv.z, bv.z));
        y.w = qv[j].w + fmaf(w1, pv.w, fmaf(w2, wv.w, bv.w));
        qv[j] = y;
        s1 += y.x + y.y + y.z + y.w;
        s2 += y.x * y.x + y.y * y.y + y.z * y.z + y.w * y.w;
    }
    s1 = wsum(s1); s2 = wsum(s2);
    const float mu = s1 * (1.f / CCH);
    const float rs = rsqrtf(s2 * (1.f / CCH) - mu * mu + 1e-5f);

    __half* qoh = g_qh + (size_t)row * CCH;
    const float4* lw4 = (const float4*)p.ln1_w;
    const float4* lb4 = (const float4*)p.ln1_b;
    #pragma unroll
    for (int j = 0; j < 4; ++j) {
        const int c4 = j * 32 + lane;
        const float4 lw = lw4[c4], lb = lb4[c4];
        float4 o;
        o.x = (qv[j].x - mu) * rs * lw.x + lb.x;
        o.y = (qv[j].y - mu) * rs * lw.y + lb.y;
        o.z = (qv[j].z - mu) * rs * lw.z + lb.z;
        o.w = (qv[j].w - mu) * rs * lw.w + lb.w;
        __half2 pk[2];
        pk[0] = __floats2half2_rn(o.x, o.y);
        pk[1] = __floats2half2_rn(o.z, o.w);
        *(uint2*)(qoh + 4 * c4) = *(const uint2*)pk;
    }
}

// ---------------------------------------------------------------------------
// Warp-per-row, float4 (r13 layout): out = LN2(z + b2 + query) + x
// z (half, in g_xh) and query (half, g_qh) read as packed half2 pairs.
// ---------------------------------------------------------------------------
__global__ __launch_bounds__(256) void k_ln2(Params p, float* __restrict__ out) {
    const int tid = threadIdx.x;
    const int lane = tid & 31, w = tid >> 5;
    const int row = blockIdx.x * 8 + w;
    const __half* zr = g_xh + (size_t)row * CCH;
    const __half* qr = g_qh + (size_t)row * CCH;
    const float4* xr4 = (const float4*)(p.x + (size_t)row * CCH);
    const float4* b24 = (const float4*)p.b2;

    float4 yv[4];
    float s1 = 0.f, s2 = 0.f;
    #pragma unroll
    for (int j = 0; j < 4; ++j) {
        const int c4 = j * 32 + lane;
        const uint2 zp = *(const uint2*)(zr + 4 * c4);
        const uint2 qp = *(const uint2*)(qr + 4 * c4);
        const __half2* zh = (const __half2*)&zp;
        const __half2* qh = (const __half2*)&qp;
        const float2 z0 = __half22float2(zh[0]);
        const float2 z1 = __half22float2(zh[1]);
        const float2 q0 = __half22float2(qh[0]);
        const float2 q1 = __half22float2(qh[1]);
        const float4 b4 = b24[c4];
        float4 y;
        y.x = z0.x + b4.x + q0.x;
        y.y = z0.y + b4.y + q0.y;
        y.z = z1.x + b4.z + q1.x;
        y.w = z1.y + b4.w + q1.y;
        yv[j] = y;
        s1 += y.x + y.y + y.z + y.w;
        s2 += y.x * y.x + y.y * y.y + y.z * y.z + y.w * y.w;
    }
    s1 = wsum(s1); s2 = wsum(s2);
    const float mu = s1 * (1.f / CCH);
    const float rs = rsqrtf(s2 * (1.f / CCH) - mu * mu + 1e-5f);

    float4* o4 = (float4*)(out + (size_t)row * CCH);
    const float4* lw4 = (const float4*)p.ln2_w;
    const float4* lb4 = (const float4*)p.ln2_b;
    #pragma unroll
    for (int j = 0; j < 4; ++j) {
        const int c4 = j * 32 + lane;
        const float4 lw = lw4[c4], lb = lb4[c4], x4 = xr4[c4];
        float4 o;
        o.x = (yv[j].x - mu) * rs * lw.x + lb.x + x4.x;
        o.y = (yv[j].y - mu) * rs * lw.y + lb.y + x4.y;
        o.z = (yv[j].z - mu) * rs * lw.z + lb.z + x4.z;
        o.w = (yv[j].w - mu) * rs * lw.w + lb.w + x4.w;
        o4[c4] = o;
    }
}

// ---------------------------------------------------------------------------
extern "C" void kernel_launch(void* const* d_in, const int* in_sizes, int n_in,
                              void* d_out, int out_size) {
    Params p;
    p.x        = (const float*)d_in[0];
    p.cond_emb = (const float*)d_in[1];
    p.Wq       = (const float*)d_in[2];
    p.bq       = (const float*)d_in[3];
    p.Wk       = (const float*)d_in[4];
    p.bk       = (const float*)d_in[5];
    p.Wv       = (const float*)d_in[6];
    p.bv       = (const float*)d_in[7];
    p.conv_w   = (const float*)d_in[8];
    p.conv_b   = (const float*)d_in[9];
    p.ln1_w    = (const float*)d_in[10];
    p.ln1_b    = (const float*)d_in[11];
    p.W1       = (const float*)d_in[12];
    p.b1       = (const float*)d_in[13];
    p.W2       = (const float*)d_in[14];
    p.b2       = (const float*)d_in[15];
    p.ln2_w    = (const float*)d_in[16];
    p.ln2_b    = (const float*)d_in[17];
    float* out = (float*)d_out;

    static bool attr_done = false;
    if (!attr_done) {
        cudaFuncSetAttribute(k_gemm_h<512, 0>,  cudaFuncAttributeMaxDynamicSharedMemorySize, SMEM_BYTES);
        cudaFuncSetAttribute(k_gemm_h<512, 1>,  cudaFuncAttributeMaxDynamicSharedMemorySize, SMEM_BYTES);
        cudaFuncSetAttribute(k_gemm_h<1024, 2>, cudaFuncAttributeMaxDynamicSharedMemorySize, SMEM_BYTES);
        attr_done = true;
    }

    float *dq;
    __half *dxh, *dqh, *dhh, *dWqh, *dW1h, *dW2h;
    cudaGetSymbolAddress((void**)&dq,   g_q);
    cudaGetSymbolAddress((void**)&dxh,  g_xh);
    cudaGetSymbolAddress((void**)&dqh,  g_qh);
    cudaGetSymbolAddress((void**)&dhh,  g_hh);
    cudaGetSymbolAddress((void**)&dWqh, g_Wqh);
    cudaGetSymbolAddress((void**)&dW1h, g_W1h);
    cudaGetSymbolAddress((void**)&dW2h, g_W2h);

    k_precompute<<<dim3(BB + 1, 2), 256>>>(p);
    k_f2h_all<<<BL_TOT, 256>>>(p.x, p.Wq, p.W1, p.W2, dxh, dWqh, dW1h, dW2h);

    // q = x @ Wq^T (fp32 out; bias folded into attn kernel)
    k_gemm_h<512, 0><<<dim3(MTOT / 128, 4), 256, SMEM_BYTES>>>(dxh, dWqh, nullptr, dq, CCH);
    k_attn_ln1<<<MTOT / 8, 256>>>(p);
    // h = gelu(query @ W1^T + b1) (half out)
    k_gemm_h<512, 1><<<dim3(MTOT / 128, 8), 256, SMEM_BYTES>>>(dqh, dW1h, p.b1, dhh, 2 * CCH);
    // z = h @ W2^T (HALF out; bias in ln2) -> reuse g_xh (x-half is dead now)
    k_gemm_h<1024, 2><<<dim3(MTOT / 128, 4), 256, SMEM_BYTES>>>(dhh, dW2h, nullptr, dxh, CCH);
    k_ln2<<<MTOT / 8, 256>>>(p, out);
}